// round 10
// baseline (speedup 1.0000x reference)
#include <cuda_runtime.h>

// Log-sparse causal attention, B=4, L=2048, H=8, E=D=64, fp32.
// Query l attends keys l-d for d in OFF (17 offsets), d <= l.
// Half-warp (16 lanes) processes QG=4 consecutive queries, sharing K/V row
// loads across the group (45 distinct rows instead of 68).
// Score array split lo(8)/slot8/hi(8): regs ~72, occ ~44%.
// NEW: far rows (e>=18, zero L1 reuse within the SM) loaded with __ldcs
// (streaming / evict-first) so the heavily-reused window rows (e=-3..13)
// stay resident in L1.

constexpr int Bc = 4, Lc = 2048, Hc = 8;
constexpr float SCALE = 0.125f;      // 1/sqrt(64)
constexpr int ROWSTR = Hc * 64;      // 512 elements per l-step

// 45 distinct relative rows e (row = l0 - e) covering all (j in 0..3, d in OFF)
__device__ constexpr int EREL[45] = {
    -3,-2,-1,0,1,2,3,4,5,6,7,8,9,10,11,12,13,
    18,19,20,21, 34,35,36,37, 66,67,68,69,
    130,131,132,133, 258,259,260,261, 514,515,516,517,
    1026,1027,1028,1029
};

// TIDX[ei][j] = slot t (index into OFF) with OFF[t] = EREL[ei] + j, or -1
__device__ constexpr int TIDX[45][4] = {
    {-1,-1,-1, 0}, {-1,-1, 0, 1}, {-1, 0, 1, 2}, { 0, 1, 2, 3},
    { 1, 2, 3, 4}, { 2, 3, 4, 5}, { 3, 4, 5, 6}, { 4, 5, 6, 7},
    { 5, 6, 7,-1}, { 6, 7,-1, 8}, { 7,-1, 8,-1}, {-1, 8,-1,-1},
    { 8,-1,-1,-1}, {-1,-1,-1, 9}, {-1,-1, 9,-1}, {-1, 9,-1,-1},
    { 9,-1,-1,-1},
    {-1,-1,-1,10}, {-1,-1,10,-1}, {-1,10,-1,-1}, {10,-1,-1,-1},
    {-1,-1,-1,11}, {-1,-1,11,-1}, {-1,11,-1,-1}, {11,-1,-1,-1},
    {-1,-1,-1,12}, {-1,-1,12,-1}, {-1,12,-1,-1}, {12,-1,-1,-1},
    {-1,-1,-1,13}, {-1,-1,13,-1}, {-1,13,-1,-1}, {13,-1,-1,-1},
    {-1,-1,-1,14}, {-1,-1,14,-1}, {-1,14,-1,-1}, {14,-1,-1,-1},
    {-1,-1,-1,15}, {-1,-1,15,-1}, {-1,15,-1,-1}, {15,-1,-1,-1},
    {-1,-1,-1,16}, {-1,-1,16,-1}, {-1,16,-1,-1}, {16,-1,-1,-1}
};

// Transpose-reduce of 8 values over a 16-lane half: lane u ends holding the
// full 16-lane sum of value index (u>>1)&7 (duplicated in lane pairs). 8 SHFLs.
__device__ __forceinline__ float txr8(const float* v, int lane) {
    const unsigned FULL = 0xffffffffu;
    const bool b8 = (lane & 8) != 0;
    float w[4];
    #pragma unroll
    for (int i = 0; i < 4; i++) {
        float own = b8 ? v[i + 4] : v[i];
        float oth = b8 ? v[i] : v[i + 4];
        w[i] = own + __shfl_xor_sync(FULL, oth, 8);
    }
    const bool b4 = (lane & 4) != 0;
    float x[2];
    #pragma unroll
    for (int i = 0; i < 2; i++) {
        float own = b4 ? w[i + 2] : w[i];
        float oth = b4 ? w[i] : w[i + 2];
        x[i] = own + __shfl_xor_sync(FULL, oth, 4);
    }
    const bool b2 = (lane & 2) != 0;
    float own = b2 ? x[1] : x[0];
    float oth = b2 ? x[0] : x[1];
    float y = own + __shfl_xor_sync(FULL, oth, 2);
    y += __shfl_xor_sync(FULL, y, 1);   // bit0 partner holds the same index
    return y;
}

__global__ __launch_bounds__(128, 7) void sparse_attn_ldcs(
    const float* __restrict__ Q,
    const float* __restrict__ K,
    const float* __restrict__ V,
    float* __restrict__ O)
{
    const unsigned FULL = 0xffffffffu;
    const int tid  = threadIdx.x;
    const int warp = tid >> 5;
    const int lane = tid & 31;
    const int half = lane >> 4;
    const int sub  = lane & 15;      // dim slice: floats [4*sub, 4*sub+4)

    // CTA = 32 consecutive queries of one (b,h). grid = 4*8*64 = 2048
    const int cta   = blockIdx.x;
    const int chunk = cta & 63;
    const int bh    = cta >> 6;
    const int h     = bh & 7;
    const int b     = bh >> 3;

    const int l0 = chunk * 32 + warp * 8 + half * 4;   // first of 4 queries

    const int rbase = ((b * Lc + l0) * Hc + h) * 64 + sub * 4;

    // load the 4 query rows
    float4 q0 = *reinterpret_cast<const float4*>(Q + rbase);
    float4 q1 = *reinterpret_cast<const float4*>(Q + rbase + ROWSTR);
    float4 q2 = *reinterpret_cast<const float4*>(Q + rbase + 2 * ROWSTR);
    float4 q3 = *reinterpret_cast<const float4*>(Q + rbase + 3 * ROWSTR);

    const int slot = (sub >> 1) & 7;                 // my lane's value index
    const int offlo = slot;                          // OFF[slot] for lo slots
    const int offhi = (1 << (slot + 3)) + 5;         // OFF[slot+9]: 13,21,...,1029
    const int halfbase = lane & 16;

    float ejlo[4], ejhi[4], e8r[4], inv[4];

    // ---------- Phase 1a: rows e=-3..9 -> slots 0..8 (window rows, .ca) ----------
    {
        float slo[4][8];
        float s8[4];
        #pragma unroll
        for (int ei = 0; ei < 13; ei++) {
            const int e = EREL[ei];
            const bool ok = (l0 >= e);
            const int addr = ok ? (rbase - e * ROWSTR) : rbase;  // clamped
            const float4 k = *reinterpret_cast<const float4*>(K + addr);
            #pragma unroll
            for (int j = 0; j < 4; j++) {
                const int t = TIDX[ei][j];
                if (t >= 0) {
                    const float4 qq = (j == 0) ? q0 : (j == 1) ? q1 : (j == 2) ? q2 : q3;
                    float p = qq.x * k.x;
                    p = fmaf(qq.y, k.y, p);
                    p = fmaf(qq.z, k.z, p);
                    p = fmaf(qq.w, k.w, p);
                    if (t < 8) slo[j][t] = p;
                    else       s8[j] = p;            // t == 8 exactly
                }
            }
        }
        #pragma unroll
        for (int j = 0; j < 4; j++) {
            float zlo = txr8(&slo[j][0], lane);
            float z8  = s8[j];
            z8 += __shfl_xor_sync(FULL, z8, 8);
            z8 += __shfl_xor_sync(FULL, z8, 4);
            z8 += __shfl_xor_sync(FULL, z8, 2);
            z8 += __shfl_xor_sync(FULL, z8, 1);
            ejlo[j] = (l0 + j >= offlo) ? __expf(zlo * SCALE) : 0.f;
            e8r[j]  = (l0 + j >= 9)     ? __expf(z8  * SCALE) : 0.f;
        }
    }

    // ---------- Phase 1b: rows e=10..1029 -> slots 9..16 ----------
    {
        float shi[4][8];
        // rows e=10..13 are window rows (reused): default .ca
        #pragma unroll
        for (int ei = 13; ei < 17; ei++) {
            const int e = EREL[ei];
            const bool ok = (l0 >= e);
            const int addr = ok ? (rbase - e * ROWSTR) : rbase;
            const float4 k = *reinterpret_cast<const float4*>(K + addr);
            #pragma unroll
            for (int j = 0; j < 4; j++) {
                const int t = TIDX[ei][j];
                if (t >= 0) {
                    const float4 qq = (j == 0) ? q0 : (j == 1) ? q1 : (j == 2) ? q2 : q3;
                    float p = qq.x * k.x;
                    p = fmaf(qq.y, k.y, p);
                    p = fmaf(qq.z, k.z, p);
                    p = fmaf(qq.w, k.w, p);
                    shi[j][t - 9] = p;
                }
            }
        }
        // rows e>=18: zero reuse in this SM -> streaming loads (.cs)
        #pragma unroll
        for (int ei = 17; ei < 45; ei++) {
            const int e = EREL[ei];
            const bool ok = (l0 >= e);
            const int addr = ok ? (rbase - e * ROWSTR) : rbase;
            const float4 k = __ldcs(reinterpret_cast<const float4*>(K + addr));
            #pragma unroll
            for (int j = 0; j < 4; j++) {
                const int t = TIDX[ei][j];
                if (t >= 0) {
                    const float4 qq = (j == 0) ? q0 : (j == 1) ? q1 : (j == 2) ? q2 : q3;
                    float p = qq.x * k.x;
                    p = fmaf(qq.y, k.y, p);
                    p = fmaf(qq.z, k.z, p);
                    p = fmaf(qq.w, k.w, p);
                    shi[j][t - 9] = p;
                }
            }
        }
        #pragma unroll
        for (int j = 0; j < 4; j++) {
            float zhi = txr8(&shi[j][0], lane);
            ejhi[j] = (l0 + j >= offhi) ? __expf(zhi * SCALE) : 0.f;
            // denominator: lanes u,u^1 hold duplicates -> butterfly {2,4,8}
            float sm = ejlo[j] + ejhi[j];
            sm += __shfl_xor_sync(FULL, sm, 2);
            sm += __shfl_xor_sync(FULL, sm, 4);
            sm += __shfl_xor_sync(FULL, sm, 8);
            inv[j] = __fdividef(1.f, sm + e8r[j]);
        }
    }

    // ---------- Phase 3: weighted V accumulation ----------
    float4 a0 = make_float4(0.f, 0.f, 0.f, 0.f);
    float4 a1 = a0, a2 = a0, a3 = a0;

    #pragma unroll
    for (int ei = 0; ei < 45; ei++) {
        const int e = EREL[ei];
        const bool ok = (l0 >= e);
        const int addr = ok ? (rbase - e * ROWSTR) : rbase;  // clamped
        const float4 v = (ei < 17)
            ? *reinterpret_cast<const float4*>(V + addr)          // window: .ca
            : __ldcs(reinterpret_cast<const float4*>(V + addr));  // far: .cs
        #pragma unroll
        for (int j = 0; j < 4; j++) {
            const int t = TIDX[ei][j];
            if (t >= 0) {
                float w;
                if (t == 8)      w = e8r[j];                                  // replicated
                else if (t < 8)  w = __shfl_sync(FULL, ejlo[j], halfbase + 2 * t);
                else             w = __shfl_sync(FULL, ejhi[j], halfbase + 2 * (t - 9));
                // w == 0 exactly for invalid uses -> clamped v is harmless
                float4& a = (j == 0) ? a0 : (j == 1) ? a1 : (j == 2) ? a2 : a3;
                a.x = fmaf(w, v.x, a.x);
                a.y = fmaf(w, v.y, a.y);
                a.z = fmaf(w, v.z, a.z);
                a.w = fmaf(w, v.w, a.w);
            }
        }
    }

    a0.x *= inv[0]; a0.y *= inv[0]; a0.z *= inv[0]; a0.w *= inv[0];
    a1.x *= inv[1]; a1.y *= inv[1]; a1.z *= inv[1]; a1.w *= inv[1];
    a2.x *= inv[2]; a2.y *= inv[2]; a2.z *= inv[2]; a2.w *= inv[2];
    a3.x *= inv[3]; a3.y *= inv[3]; a3.z *= inv[3]; a3.w *= inv[3];

    *reinterpret_cast<float4*>(O + rbase)              = a0;
    *reinterpret_cast<float4*>(O + rbase + ROWSTR)     = a1;
    *reinterpret_cast<float4*>(O + rbase + 2 * ROWSTR) = a2;
    *reinterpret_cast<float4*>(O + rbase + 3 * ROWSTR) = a3;
}

extern "C" void kernel_launch(void* const* d_in, const int* in_sizes, int n_in,
                              void* d_out, int out_size)
{
    const float* Q = (const float*)d_in[0];
    const float* K = (const float*)d_in[1];
    const float* V = (const float*)d_in[2];
    float* O = (float*)d_out;

    const int nblocks = Bc * Hc * (Lc / 32); // 2048
    sparse_attn_ldcs<<<nblocks, 128>>>(Q, K, V, O);
}

// round 11
// speedup vs baseline: 1.0120x; 1.0120x over previous
#include <cuda_runtime.h>

// Log-sparse causal attention, B=4, L=2048, H=8, E=D=64, fp32.
// Query l attends keys l-d for d in OFF (17 offsets), d <= l.
// QG=8: a 16-lane half-warp processes 8 consecutive queries, sharing K/V row
// loads across the group: 77 distinct rows per 8 queries (vs 90 for 2x QG4).
// Loads unconditional clamped-address (predication kills batching - R6).
// Phase 1a: rows e=-7..9  -> slots 0..8 (+ slot9 partials for j>=4).
// Phase 1b: rows e=10..21 + 6 far groups -> slots 9..16.
// Phase 3: all 77 rows again for V, weights broadcast from lane pairs.

constexpr int Bc = 4, Lc = 2048, Hc = 8;
constexpr float SCALE = 0.125f;      // 1/sqrt(64)
constexpr int ROWSTR = Hc * 64;      // 512 elements per l-step

// Dense rows: e = -7..21 (indices 0..28). TD8[r][j] = slot t with OFF[t]==e+j, or -1.
// OFF = {0..7, 9, 13, 21, 37, 69, 133, 261, 517, 1029}; t: 0..7,8(=9),9(=13),10(=21),...
__device__ constexpr signed char TD8[29][8] = {
    {-1,-1,-1,-1,-1,-1,-1, 0},  // e=-7
    {-1,-1,-1,-1,-1,-1, 0, 1},  // e=-6
    {-1,-1,-1,-1,-1, 0, 1, 2},  // e=-5
    {-1,-1,-1,-1, 0, 1, 2, 3},  // e=-4
    {-1,-1,-1, 0, 1, 2, 3, 4},  // e=-3
    {-1,-1, 0, 1, 2, 3, 4, 5},  // e=-2
    {-1, 0, 1, 2, 3, 4, 5, 6},  // e=-1
    { 0, 1, 2, 3, 4, 5, 6, 7},  // e=0
    { 1, 2, 3, 4, 5, 6, 7,-1},  // e=1
    { 2, 3, 4, 5, 6, 7,-1, 8},  // e=2
    { 3, 4, 5, 6, 7,-1, 8,-1},  // e=3
    { 4, 5, 6, 7,-1, 8,-1,-1},  // e=4
    { 5, 6, 7,-1, 8,-1,-1,-1},  // e=5
    { 6, 7,-1, 8,-1,-1,-1, 9},  // e=6
    { 7,-1, 8,-1,-1,-1, 9,-1},  // e=7
    {-1, 8,-1,-1,-1, 9,-1,-1},  // e=8
    { 8,-1,-1,-1, 9,-1,-1,-1},  // e=9
    {-1,-1,-1, 9,-1,-1,-1,-1},  // e=10
    {-1,-1, 9,-1,-1,-1,-1,-1},  // e=11
    {-1, 9,-1,-1,-1,-1,-1,-1},  // e=12
    { 9,-1,-1,-1,-1,-1,-1,-1},  // e=13
    {-1,-1,-1,-1,-1,-1,-1,10},  // e=14
    {-1,-1,-1,-1,-1,-1,10,-1},  // e=15
    {-1,-1,-1,-1,-1,10,-1,-1},  // e=16
    {-1,-1,-1,-1,10,-1,-1,-1},  // e=17
    {-1,-1,-1,10,-1,-1,-1,-1},  // e=18
    {-1,-1,10,-1,-1,-1,-1,-1},  // e=19
    {-1,10,-1,-1,-1,-1,-1,-1},  // e=20
    {10,-1,-1,-1,-1,-1,-1,-1},  // e=21
};

// Transpose-reduce of 8 values over a 16-lane half: lane u ends holding the
// full 16-lane sum of value index (u>>1)&7 (duplicated in lane pairs). 8 SHFLs.
__device__ __forceinline__ float txr8(const float* v, int lane) {
    const unsigned FULL = 0xffffffffu;
    const bool b8 = (lane & 8) != 0;
    float w[4];
    #pragma unroll
    for (int i = 0; i < 4; i++) {
        float own = b8 ? v[i + 4] : v[i];
        float oth = b8 ? v[i] : v[i + 4];
        w[i] = own + __shfl_xor_sync(FULL, oth, 8);
    }
    const bool b4 = (lane & 4) != 0;
    float x[2];
    #pragma unroll
    for (int i = 0; i < 2; i++) {
        float own = b4 ? w[i + 2] : w[i];
        float oth = b4 ? w[i] : w[i + 2];
        x[i] = own + __shfl_xor_sync(FULL, oth, 4);
    }
    const bool b2 = (lane & 2) != 0;
    float own = b2 ? x[1] : x[0];
    float oth = b2 ? x[0] : x[1];
    float y = own + __shfl_xor_sync(FULL, oth, 2);
    y += __shfl_xor_sync(FULL, y, 1);   // bit0 partner holds the same index
    return y;
}

__global__ __launch_bounds__(128, 3) void sparse_attn_qg8(
    const float* __restrict__ Q,
    const float* __restrict__ K,
    const float* __restrict__ V,
    float* __restrict__ O)
{
    const unsigned FULL = 0xffffffffu;
    const int tid  = threadIdx.x;
    const int warp = tid >> 5;
    const int lane = tid & 31;
    const int half = lane >> 4;
    const int sub  = lane & 15;      // dim slice: floats [4*sub, 4*sub+4)

    // CTA = 64 consecutive queries of one (b,h). grid = 4*8*32 = 1024
    const int cta   = blockIdx.x;
    const int chunk = cta & 31;
    const int bh    = cta >> 5;
    const int h     = bh & 7;
    const int b     = bh >> 3;

    const int l0 = chunk * 64 + warp * 16 + half * 8;  // first of 8 queries

    const int rbase = ((b * Lc + l0) * Hc + h) * 64 + sub * 4;

    // load the 8 query rows
    float4 q[8];
    #pragma unroll
    for (int j = 0; j < 8; j++)
        q[j] = *reinterpret_cast<const float4*>(Q + rbase + j * ROWSTR);

    const int slot = (sub >> 1) & 7;                 // my lane pair's value index
    const int offlo = slot;                          // OFF for lo slots 0..7
    const int offhi = (1 << (slot + 3)) + 5;         // OFF for hi slots: 13,21,...,1029
    const int halfbase = lane & 16;

    float ejlo[8], ejhi[8], e8r[8], inv[8];
    float shi[8][8];   // hi slots: [0]=d13, [1]=d21, [2]=d37 ... [7]=d1029

    // ---------- Phase 1a: dense rows e=-7..9 -> slots 0..8 (+ slot9 j>=4) ----------
    {
        float slo[8][8];
        float s8[8];
        #pragma unroll
        for (int r = 0; r < 17; r++) {               // e = r - 7
            const int e = r - 7;
            const bool ok = (l0 >= e);
            const int addr = ok ? (rbase - e * ROWSTR) : rbase;   // clamped
            const float4 k = *reinterpret_cast<const float4*>(K + addr);
            #pragma unroll
            for (int j = 0; j < 8; j++) {
                const int t = TD8[r][j];
                if (t >= 0) {
                    float p = q[j].x * k.x;
                    p = fmaf(q[j].y, k.y, p);
                    p = fmaf(q[j].z, k.z, p);
                    p = fmaf(q[j].w, k.w, p);
                    if (t < 8)       slo[j][t] = p;
                    else if (t == 8) s8[j] = p;
                    else             shi[j][0] = p;  // t==9, j>=4
                }
            }
        }
        #pragma unroll
        for (int j = 0; j < 8; j++) {
            float zlo = txr8(&slo[j][0], lane);
            float z8  = s8[j];
            z8 += __shfl_xor_sync(FULL, z8, 8);
            z8 += __shfl_xor_sync(FULL, z8, 4);
            z8 += __shfl_xor_sync(FULL, z8, 2);
            z8 += __shfl_xor_sync(FULL, z8, 1);
            ejlo[j] = (l0 + j >= offlo) ? __expf(zlo * SCALE) : 0.f;
            e8r[j]  = (l0 + j >= 9)     ? __expf(z8  * SCALE) : 0.f;
        }
    }

    // ---------- Phase 1b: rows e=10..21 + far groups -> slots 9..16 ----------
    {
        #pragma unroll
        for (int r = 17; r < 29; r++) {              // e = 10..21
            const int e = r - 7;
            const bool ok = (l0 >= e);
            const int addr = ok ? (rbase - e * ROWSTR) : rbase;
            const float4 k = *reinterpret_cast<const float4*>(K + addr);
            #pragma unroll
            for (int j = 0; j < 8; j++) {
                const int t = TD8[r][j];
                if (t >= 0) {
                    float p = q[j].x * k.x;
                    p = fmaf(q[j].y, k.y, p);
                    p = fmaf(q[j].z, k.z, p);
                    p = fmaf(q[j].w, k.w, p);
                    shi[j][t - 9] = p;               // t = 9 or 10
                }
            }
        }
        // far groups g=1..6: d = (1<<(g+4))+5 in {37,69,133,261,517,1029}
        #pragma unroll
        for (int g = 1; g <= 6; g++) {
            const int D = (1 << (g + 4)) + 5;
            #pragma unroll
            for (int r = 0; r < 8; r++) {
                const int e = D - 7 + r;             // j = 7 - r
                const int j = 7 - r;
                const bool ok = (l0 >= e);
                const int addr = ok ? (rbase - e * ROWSTR) : rbase;
                const float4 k = *reinterpret_cast<const float4*>(K + addr);
                float p = q[j].x * k.x;
                p = fmaf(q[j].y, k.y, p);
                p = fmaf(q[j].z, k.z, p);
                p = fmaf(q[j].w, k.w, p);
                shi[j][g + 1] = p;
            }
        }
        #pragma unroll
        for (int j = 0; j < 8; j++) {
            float zhi = txr8(&shi[j][0], lane);
            ejhi[j] = (l0 + j >= offhi) ? __expf(zhi * SCALE) : 0.f;
            // denominator: lane pairs hold slots {s, s+9}; butterfly {2,4,8}
            float sm = ejlo[j] + ejhi[j];
            sm += __shfl_xor_sync(FULL, sm, 2);
            sm += __shfl_xor_sync(FULL, sm, 4);
            sm += __shfl_xor_sync(FULL, sm, 8);
            inv[j] = __fdividef(1.f, sm + e8r[j]);
        }
    }

    // ---------- Phase 3: weighted V accumulation ----------
    float4 acc[8];
    #pragma unroll
    for (int j = 0; j < 8; j++) acc[j] = make_float4(0.f, 0.f, 0.f, 0.f);

    #pragma unroll
    for (int r = 0; r < 29; r++) {                   // dense rows e=-7..21
        const int e = r - 7;
        const bool ok = (l0 >= e);
        const int addr = ok ? (rbase - e * ROWSTR) : rbase;
        const float4 v = *reinterpret_cast<const float4*>(V + addr);
        #pragma unroll
        for (int j = 0; j < 8; j++) {
            const int t = TD8[r][j];
            if (t >= 0) {
                float w;
                if (t == 8)      w = e8r[j];                                  // replicated
                else if (t < 8)  w = __shfl_sync(FULL, ejlo[j], halfbase + 2 * t);
                else             w = __shfl_sync(FULL, ejhi[j], halfbase + 2 * (t - 9));
                acc[j].x = fmaf(w, v.x, acc[j].x);
                acc[j].y = fmaf(w, v.y, acc[j].y);
                acc[j].z = fmaf(w, v.z, acc[j].z);
                acc[j].w = fmaf(w, v.w, acc[j].w);
            }
        }
    }
    #pragma unroll
    for (int g = 1; g <= 6; g++) {                   // far groups
        const int D = (1 << (g + 4)) + 5;
        #pragma unroll
        for (int r = 0; r < 8; r++) {
            const int e = D - 7 + r;
            const int j = 7 - r;
            const bool ok = (l0 >= e);
            const int addr = ok ? (rbase - e * ROWSTR) : rbase;
            const float4 v = *reinterpret_cast<const float4*>(V + addr);
            const float w = __shfl_sync(FULL, ejhi[j], halfbase + 2 * (g + 1));
            acc[j].x = fmaf(w, v.x, acc[j].x);
            acc[j].y = fmaf(w, v.y, acc[j].y);
            acc[j].z = fmaf(w, v.z, acc[j].z);
            acc[j].w = fmaf(w, v.w, acc[j].w);
        }
    }

    #pragma unroll
    for (int j = 0; j < 8; j++) {
        float4 o;
        o.x = acc[j].x * inv[j];
        o.y = acc[j].y * inv[j];
        o.z = acc[j].z * inv[j];
        o.w = acc[j].w * inv[j];
        *reinterpret_cast<float4*>(O + rbase + j * ROWSTR) = o;
    }
}

extern "C" void kernel_launch(void* const* d_in, const int* in_sizes, int n_in,
                              void* d_out, int out_size)
{
    const float* Q = (const float*)d_in[0];
    const float* K = (const float*)d_in[1];
    const float* V = (const float*)d_in[2];
    float* O = (float*)d_out;

    const int nblocks = Bc * Hc * (Lc / 64); // 1024
    sparse_attn_qg8<<<nblocks, 128>>>(Q, K, V, O);
}